// round 16
// baseline (speedup 1.0000x reference)
#include <cuda_runtime.h>
#include <cuda_bf16.h>
#include <cuda_fp16.h>
#include <mma.h>
#include <cstdint>

using namespace nvcuda;

#define DEVINL __device__ __forceinline__

static constexpr int B_ = 8;
static constexpr int L_ = 2048;
static constexpr int D_ = 128;
static constexpr int NT = 256;    // scores threads (8 warps)
static constexpr int PT = 256;    // proj threads (8 warps)

// Padded strides (elements)
static constexpr int LDB = 136;   // 16-bit tiles: 272B rows
static constexpr int LDC = 132;   // f32 staging rows

static constexpr int TILE_BYTES = 128 * LDB * 2;    // 34816
static constexpr int TILE64_BYTES = 64 * LDB * 2;   // 17408

// ---- scores kernel smem: 2 tile slots (69632 B), 3 CTAs/SM ----
static constexpr int S0 = 0;
static constexpr int S2 = S0 + TILE_BYTES;
static constexpr int S_SMEM = S2 + TILE_BYTES;      // 69632 (x3 = 208896)

// ---- proj kernel smem (64-row X tile, 2 CTAs/SM) ----
static constexpr int P_XH = 0;                      // 64-row tile
static constexpr int P_XL = P_XH + TILE64_BYTES;
static constexpr int P_WH = P_XL + TILE64_BYTES;    // 128-row tile
static constexpr int P_WL = P_WH + TILE_BYTES;
static constexpr int P_BIAS = P_WL + TILE_BYTES;    // 104448
static constexpr int P_SMEM = P_BIAS + 512;         // 104960
static constexpr int P_C = P_XH;                    // overlay: 33792 <= 34816

// ---------------------------------------------------------------------------
// Scratch: projection outputs, single fp16 (p: qm=0, km=1, qs=2, ks=3), 16 MB.
// ---------------------------------------------------------------------------
__device__ __align__(16) __half g_p[4][(size_t)B_ * L_ * D_];

// ---------------------------------------------------------------------------
DEVINL void cp_async16(uint32_t dst, const void* src) {
    asm volatile("cp.async.cg.shared.global [%0], [%1], 16;" :: "r"(dst), "l"(src) : "memory");
}
DEVINL void cp_commit() { asm volatile("cp.async.commit_group;" ::: "memory"); }
template <int N>
DEVINL void cp_wait_group() { asm volatile("cp.async.wait_group %0;" :: "n"(N) : "memory"); }
DEVINL uint32_t smem_u32(const void* p) {
    uint32_t a;
    asm("{ .reg .u64 t; cvta.to.shared.u64 t, %1; cvt.u32.u64 %0, t; }" : "=r"(a) : "l"(p));
    return a;
}

// bf16 split (proj-internal MMA tiles)
DEVINL uint32_t pack2b(__nv_bfloat16 a, __nv_bfloat16 b) {
    return (uint32_t)__bfloat16_as_ushort(a) | ((uint32_t)__bfloat16_as_ushort(b) << 16);
}
DEVINL void split2(float a, float b, uint32_t& h, uint32_t& l) {
    __nv_bfloat16 ha = __float2bfloat16_rn(a);
    __nv_bfloat16 hb = __float2bfloat16_rn(b);
    __nv_bfloat16 la = __float2bfloat16_rn(a - __bfloat162float(ha));
    __nv_bfloat16 lb = __float2bfloat16_rn(b - __bfloat162float(hb));
    h = pack2b(ha, hb);
    l = pack2b(la, lb);
}
DEVINL uint32_t pack2h(__half a, __half b) {
    return (uint32_t)__half_as_ushort(a) | ((uint32_t)__half_as_ushort(b) << 16);
}

// HW tanh: single MUFU.TANH, abs err ~2^-11
DEVINL float tanh_hw(float x) {
    float r;
    asm("tanh.approx.f32 %0, %1;" : "=f"(r) : "f"(x));
    return r;
}

// Load ROWS x 128 16-bit tile (row-major 256B rows) into padded smem (272B rows).
template <int ROWS, int THREADS>
DEVINL void load_tile_cp(uint32_t dst, const void* src, int tid) {
    const char* s = reinterpret_cast<const char*>(src);
#pragma unroll
    for (int i = 0; i < ROWS * 16 / THREADS; i++) {
        int idx = i * THREADS + tid;
        int r = idx >> 4, c = idx & 15;
        cp_async16(dst + r * 272 + c * 16, s + r * 256 + c * 16);
    }
}

typedef wmma::fragment<wmma::matrix_a, 16, 16, 16, __nv_bfloat16, wmma::row_major> FragAb;
typedef wmma::fragment<wmma::matrix_b, 16, 16, 16, __nv_bfloat16, wmma::row_major> FragBrb;
typedef wmma::fragment<wmma::matrix_a, 16, 16, 16, __half, wmma::row_major> FragAh;
typedef wmma::fragment<wmma::matrix_b, 16, 16, 16, __half, wmma::col_major> FragBch;
typedef wmma::fragment<wmma::accumulator, 16, 16, 16, float> FragC;

// ---------------------------------------------------------------------------
// Kernel 1: projections Y = X @ W + b.  3-pass bf16 MMA (near-fp32 accuracy),
// output stored as single fp16. CTA: 64-row X tile, 2x4 warp grid, 2 CTAs/SM.
// ---------------------------------------------------------------------------
__global__ __launch_bounds__(PT, 2)
void proj_kernel(const float* __restrict__ query, const float* __restrict__ key,
                 const float* __restrict__ wqm, const float* __restrict__ bqm,
                 const float* __restrict__ wkm, const float* __restrict__ bkm,
                 const float* __restrict__ wqs, const float* __restrict__ bqs,
                 const float* __restrict__ wks, const float* __restrict__ bks) {
    extern __shared__ __align__(16) char smem[];
    const int tid = threadIdx.x, wid = tid >> 5;
    const int p = blockIdx.y;
    const int m0 = blockIdx.x * 64;

    const float* src  = (p & 1) ? key : query;
    const float* W    = (p == 0) ? wqm : (p == 1) ? wkm : (p == 2) ? wqs : wks;
    const float* bias = (p == 0) ? bqm : (p == 1) ? bkm : (p == 2) ? bqs : bks;

    float* sbias = reinterpret_cast<float*>(smem + P_BIAS);
    if (tid < 128) sbias[tid] = bias[tid];

    // X (64x128): f32 -> bf16 hi/lo split
#pragma unroll
    for (int i = 0; i < 4; i++) {
        int idx = i * PT + tid;
        int r = idx >> 4, c = idx & 15;
        const float* sp = src + (size_t)(m0 + r) * D_ + c * 8;
        float4 v0 = *reinterpret_cast<const float4*>(sp);
        float4 v1 = *reinterpret_cast<const float4*>(sp + 4);
        uint4 H, Lo;
        split2(v0.x, v0.y, H.x, Lo.x);
        split2(v0.z, v0.w, H.y, Lo.y);
        split2(v1.x, v1.y, H.z, Lo.z);
        split2(v1.z, v1.w, H.w, Lo.w);
        *reinterpret_cast<uint4*>(smem + P_XH + r * 272 + c * 16) = H;
        *reinterpret_cast<uint4*>(smem + P_XL + r * 272 + c * 16) = Lo;
    }
    // W (128x128): f32 -> bf16 hi/lo split
#pragma unroll
    for (int i = 0; i < 8; i++) {
        int idx = i * PT + tid;
        int r = idx >> 4, c = idx & 15;
        const float* sp = W + (size_t)r * D_ + c * 8;
        float4 v0 = *reinterpret_cast<const float4*>(sp);
        float4 v1 = *reinterpret_cast<const float4*>(sp + 4);
        uint4 H, Lo;
        split2(v0.x, v0.y, H.x, Lo.x);
        split2(v0.z, v0.w, H.y, Lo.y);
        split2(v1.x, v1.y, H.z, Lo.z);
        split2(v1.z, v1.w, H.w, Lo.w);
        *reinterpret_cast<uint4*>(smem + P_WH + r * 272 + c * 16) = H;
        *reinterpret_cast<uint4*>(smem + P_WL + r * 272 + c * 16) = Lo;
    }
    __syncthreads();

    const int wm = wid & 1, wn = wid >> 1;   // 2 x 4 warp grid -> 32 x 32 each
    const __nv_bfloat16* sXh = reinterpret_cast<const __nv_bfloat16*>(smem + P_XH);
    const __nv_bfloat16* sXl = reinterpret_cast<const __nv_bfloat16*>(smem + P_XL);
    const __nv_bfloat16* sWh = reinterpret_cast<const __nv_bfloat16*>(smem + P_WH);
    const __nv_bfloat16* sWl = reinterpret_cast<const __nv_bfloat16*>(smem + P_WL);

    FragC acc[2][2];
#pragma unroll
    for (int i = 0; i < 2; i++)
#pragma unroll
        for (int j = 0; j < 2; j++) wmma::fill_fragment(acc[i][j], 0.0f);

#pragma unroll
    for (int k = 0; k < 8; k++) {
        FragAb ah[2], al[2];
        wmma::load_matrix_sync(ah[0], sXh + (wm * 32 + 0) * LDB + k * 16, LDB);
        wmma::load_matrix_sync(ah[1], sXh + (wm * 32 + 16) * LDB + k * 16, LDB);
        wmma::load_matrix_sync(al[0], sXl + (wm * 32 + 0) * LDB + k * 16, LDB);
        wmma::load_matrix_sync(al[1], sXl + (wm * 32 + 16) * LDB + k * 16, LDB);
#pragma unroll
        for (int j = 0; j < 2; j++) {
            FragBrb bh, bl;
            wmma::load_matrix_sync(bh, sWh + (k * 16) * LDB + (wn * 32 + j * 16), LDB);
            wmma::load_matrix_sync(bl, sWl + (k * 16) * LDB + (wn * 32 + j * 16), LDB);
            wmma::mma_sync(acc[0][j], ah[0], bh, acc[0][j]);
            wmma::mma_sync(acc[1][j], ah[1], bh, acc[1][j]);
            wmma::mma_sync(acc[0][j], al[0], bh, acc[0][j]);
            wmma::mma_sync(acc[1][j], al[1], bh, acc[1][j]);
            wmma::mma_sync(acc[0][j], ah[0], bl, acc[0][j]);
            wmma::mma_sync(acc[1][j], ah[1], bl, acc[1][j]);
        }
    }
    __syncthreads();

    // C -> smem overlay (X area no longer needed)
    float* Cs = reinterpret_cast<float*>(smem + P_C);
#pragma unroll
    for (int i = 0; i < 2; i++)
#pragma unroll
        for (int j = 0; j < 2; j++)
            wmma::store_matrix_sync(Cs + (wm * 32 + i * 16) * LDC + (wn * 32 + j * 16),
                                    acc[i][j], LDC, wmma::mem_row_major);
    __syncthreads();

    // epilogue: + bias, fp16 round, store scratch (64 rows)
#pragma unroll
    for (int i = 0; i < 8; i++) {
        int u = i * PT + tid;
        int r = u >> 5, c4 = (u & 31) << 2;
        float4 v = *reinterpret_cast<const float4*>(Cs + r * LDC + c4);
        v.x += sbias[c4 + 0];
        v.y += sbias[c4 + 1];
        v.z += sbias[c4 + 2];
        v.w += sbias[c4 + 3];
        uint32_t h01 = pack2h(__float2half_rn(v.x), __float2half_rn(v.y));
        uint32_t h23 = pack2h(__float2half_rn(v.z), __float2half_rn(v.w));
        size_t o = (size_t)(m0 + r) * D_ + c4;
        *reinterpret_cast<uint2*>(g_p[p] + o) = make_uint2(h01, h23);
    }
}

// ---------------------------------------------------------------------------
// Kernel 2: scores. CTA = 128x128 S tile for ONE phase (mean or std).
// 3 CTAs/SM (2 tile slots). Single-pass fp16 GEMM, fp32 accumulate.
// Mask loaded DIRECTLY from gmem as accumulator fragments (ld = L_) while the
// cp.async tile loads fly; bit-tested via __float_as_uint (int 1 = denormal).
// One barrier total.
// ---------------------------------------------------------------------------
__global__ __launch_bounds__(NT, 3)
void scores_kernel(const int* __restrict__ mask, float* __restrict__ out) {
    extern __shared__ __align__(16) char smem[];
    const int tid = threadIdx.x, wid = tid >> 5;
    const int nb0 = blockIdx.x * 128;
    const int mb0 = blockIdx.y * 128;
    const int b = blockIdx.z >> 1;
    const int phase = blockIdx.z & 1;
    const uint32_t sbase = smem_u32(smem);
    const int wm = wid & 3, wn = wid >> 2;   // 4 x 2 -> 32 x 64 per warp
    const float inv_sqrt_d = 0.08838834764831845f;

    const size_t qoff = ((size_t)b * L_ + mb0) * D_;
    const size_t koff = ((size_t)b * L_ + nb0) * D_;
    const int pq = 2 * phase, pk = 2 * phase + 1;

    // Issue tile loads first; mask fragment loads overlap their latency.
    load_tile_cp<128, NT>(sbase + S0, g_p[pq] + qoff, tid);
    load_tile_cp<128, NT>(sbase + S2, g_p[pk] + koff, tid);
    cp_commit();

    // Mask -> per-lane bitmask, fragments loaded straight from gmem.
    const float* Mg = reinterpret_cast<const float*>(mask)
                    + ((size_t)b * L_ + mb0) * L_ + nb0;
    uint32_t mbits[2] = {0u, 0u};
#pragma unroll
    for (int i = 0; i < 2; i++)
#pragma unroll
        for (int j = 0; j < 4; j++) {
            FragC mf;
            wmma::load_matrix_sync(mf, Mg + (size_t)(wm * 32 + i * 16) * L_ + (wn * 64 + j * 16),
                                   L_, wmma::mem_row_major);
#pragma unroll
            for (int e = 0; e < 8; e++)
                mbits[i] |= (__float_as_uint(mf.x[e]) != 0u ? 1u : 0u) << (j * 8 + e);
        }

    cp_wait_group<0>();
    __syncthreads();   // tiles ready (only barrier)

    const __half* Qh = reinterpret_cast<const __half*>(smem + S0);
    const __half* Kh = reinterpret_cast<const __half*>(smem + S2);

    FragC acc[2][4];
#pragma unroll
    for (int i = 0; i < 2; i++)
#pragma unroll
        for (int j = 0; j < 4; j++) wmma::fill_fragment(acc[i][j], 0.0f);

#pragma unroll
    for (int k = 0; k < 8; k++) {
        FragAh a[2];
        wmma::load_matrix_sync(a[0], Qh + (wm * 32 + 0) * LDB + k * 16, LDB);
        wmma::load_matrix_sync(a[1], Qh + (wm * 32 + 16) * LDB + k * 16, LDB);
#pragma unroll
        for (int j = 0; j < 4; j++) {
            FragBch bf;   // K row-major [n][k] == col-major (k,n)
            wmma::load_matrix_sync(bf, Kh + (wn * 64 + j * 16) * LDB + k * 16, LDB);
            wmma::mma_sync(acc[0][j], a[0], bf, acc[0][j]);
            wmma::mma_sync(acc[1][j], a[1], bf, acc[1][j]);
        }
    }

    // epilogue: FMUL -> MUFU.TANH -> FFMA -> select -> store
    const float sA = phase ? 4.0f : 0.5f;
    const float sB = phase ? -6.0f : 0.5f;
    const float sC = phase ? -10.0f : 0.0f;
    float* obase = out + (size_t)phase * B_ * L_ * L_ + (size_t)b * L_ * L_;
#pragma unroll
    for (int i = 0; i < 2; i++) {
#pragma unroll
        for (int j = 0; j < 4; j++) {
            int r0 = wm * 32 + i * 16, c0 = wn * 64 + j * 16;
#pragma unroll
            for (int e = 0; e < 8; e++) {
                float tt = tanh_hw(acc[i][j].x[e] * inv_sqrt_d);
                bool m = (mbits[i] >> (j * 8 + e)) & 1u;
                acc[i][j].x[e] = m ? fmaf(sA, tt, sB) : sC;
            }
            wmma::store_matrix_sync(obase + (size_t)(mb0 + r0) * L_ + (nb0 + c0),
                                    acc[i][j], L_, wmma::mem_row_major);
        }
    }
}

// ---------------------------------------------------------------------------
extern "C" void kernel_launch(void* const* d_in, const int* in_sizes, int n_in,
                              void* d_out, int out_size) {
    const float* query = (const float*)d_in[0];
    const float* key   = (const float*)d_in[1];
    const int*   mask  = (const int*)d_in[2];
    const float* wqm = (const float*)d_in[3];
    const float* bqm = (const float*)d_in[4];
    const float* wkm = (const float*)d_in[5];
    const float* bkm = (const float*)d_in[6];
    const float* wqs = (const float*)d_in[7];
    const float* bqs = (const float*)d_in[8];
    const float* wks = (const float*)d_in[9];
    const float* bks = (const float*)d_in[10];
    float* out = (float*)d_out;

    cudaFuncSetAttribute(proj_kernel, cudaFuncAttributeMaxDynamicSharedMemorySize, P_SMEM);
    cudaFuncSetAttribute(scores_kernel, cudaFuncAttributeMaxDynamicSharedMemorySize, S_SMEM);

    proj_kernel<<<dim3((B_ * L_) / 64, 4), PT, P_SMEM>>>(
        query, key, wqm, bqm, wkm, bkm, wqs, bqs, wks, bks);
    scores_kernel<<<dim3(L_ / 128, L_ / 128, 2 * B_), NT, S_SMEM>>>(mask, out);
}

// round 17
// speedup vs baseline: 1.8031x; 1.8031x over previous
#include <cuda_runtime.h>
#include <cuda_bf16.h>
#include <cuda_fp16.h>
#include <mma.h>
#include <cstdint>

using namespace nvcuda;

#define DEVINL __device__ __forceinline__

static constexpr int B_ = 8;
static constexpr int L_ = 2048;
static constexpr int D_ = 128;
static constexpr int NT = 256;    // scores threads (8 warps)
static constexpr int PT = 256;    // proj threads (8 warps)

// Padded strides (elements)
static constexpr int LDB = 136;   // 16-bit tiles: 272B rows
static constexpr int LDC = 132;   // f32 staging rows

static constexpr int TILE_BYTES = 128 * LDB * 2;    // 34816
static constexpr int TILE64_BYTES = 64 * LDB * 2;   // 17408

// ---- scores kernel smem: 3 slots (104448 B), 2 CTAs/SM ----
// S0=Qh tile, S2=Kh tile, S1 = 64-row f32 mask staging (33792 <= 34816)
static constexpr int S0 = 0;
static constexpr int S1 = S0 + TILE_BYTES;
static constexpr int S2 = S1 + TILE_BYTES;
static constexpr int S_SMEM = S2 + TILE_BYTES;      // 104448 (x2 <= 228KB)

// ---- proj kernel smem (64-row X tile + bf16 W tiles via cp.async) ----
static constexpr int P_XH = 0;                      // 64-row tile
static constexpr int P_XL = P_XH + TILE64_BYTES;
static constexpr int P_WH = P_XL + TILE64_BYTES;    // 128-row tile (cp.async)
static constexpr int P_WL = P_WH + TILE_BYTES;
static constexpr int P_BIAS = P_WL + TILE_BYTES;    // 104448
static constexpr int P_SMEM = P_BIAS + 512;         // 104960 (x2 = 209920)
static constexpr int P_C = P_XH;                    // overlay: 33792 <= 34816

// ---------------------------------------------------------------------------
// Scratch: projection outputs fp16 (p: qm=0, km=1, qs=2, ks=3), 16 MB.
// Weight splits: bf16 hi/lo, [k][n] row-major, 4 x 32 KB x2.
// ---------------------------------------------------------------------------
__device__ __align__(16) __half g_p[4][(size_t)B_ * L_ * D_];
__device__ __align__(16) __nv_bfloat16 g_wh[4][D_ * D_];
__device__ __align__(16) __nv_bfloat16 g_wl[4][D_ * D_];

// ---------------------------------------------------------------------------
DEVINL void cp_async16(uint32_t dst, const void* src) {
    asm volatile("cp.async.cg.shared.global [%0], [%1], 16;" :: "r"(dst), "l"(src) : "memory");
}
DEVINL void cp_commit() { asm volatile("cp.async.commit_group;" ::: "memory"); }
template <int N>
DEVINL void cp_wait_group() { asm volatile("cp.async.wait_group %0;" :: "n"(N) : "memory"); }
DEVINL uint32_t smem_u32(const void* p) {
    uint32_t a;
    asm("{ .reg .u64 t; cvta.to.shared.u64 t, %1; cvt.u32.u64 %0, t; }" : "=r"(a) : "l"(p));
    return a;
}

// bf16 split
DEVINL uint32_t pack2b(__nv_bfloat16 a, __nv_bfloat16 b) {
    return (uint32_t)__bfloat16_as_ushort(a) | ((uint32_t)__bfloat16_as_ushort(b) << 16);
}
DEVINL void split2(float a, float b, uint32_t& h, uint32_t& l) {
    __nv_bfloat16 ha = __float2bfloat16_rn(a);
    __nv_bfloat16 hb = __float2bfloat16_rn(b);
    __nv_bfloat16 la = __float2bfloat16_rn(a - __bfloat162float(ha));
    __nv_bfloat16 lb = __float2bfloat16_rn(b - __bfloat162float(hb));
    h = pack2b(ha, hb);
    l = pack2b(la, lb);
}
DEVINL uint32_t pack2h(__half a, __half b) {
    return (uint32_t)__half_as_ushort(a) | ((uint32_t)__half_as_ushort(b) << 16);
}

// HW tanh: single MUFU.TANH, abs err ~2^-11
DEVINL float tanh_hw(float x) {
    float r;
    asm("tanh.approx.f32 %0, %1;" : "=f"(r) : "f"(x));
    return r;
}

// Load ROWS x 128 16-bit tile (row-major 256B rows) into padded smem (272B rows).
template <int ROWS, int THREADS>
DEVINL void load_tile_cp(uint32_t dst, const void* src, int tid) {
    const char* s = reinterpret_cast<const char*>(src);
#pragma unroll
    for (int i = 0; i < ROWS * 16 / THREADS; i++) {
        int idx = i * THREADS + tid;
        int r = idx >> 4, c = idx & 15;
        cp_async16(dst + r * 272 + c * 16, s + r * 256 + c * 16);
    }
}

typedef wmma::fragment<wmma::matrix_a, 16, 16, 16, __nv_bfloat16, wmma::row_major> FragAb;
typedef wmma::fragment<wmma::matrix_b, 16, 16, 16, __nv_bfloat16, wmma::row_major> FragBrb;
typedef wmma::fragment<wmma::matrix_a, 16, 16, 16, __half, wmma::row_major> FragAh;
typedef wmma::fragment<wmma::matrix_b, 16, 16, 16, __half, wmma::col_major> FragBch;
typedef wmma::fragment<wmma::accumulator, 16, 16, 16, float> FragC;

// ---------------------------------------------------------------------------
// Kernel 0: split the four [D,D] weight matrices to bf16 hi/lo (kept [k][n]).
// ---------------------------------------------------------------------------
__global__ void wprep_kernel(const float* __restrict__ wqm, const float* __restrict__ wkm,
                             const float* __restrict__ wqs, const float* __restrict__ wks) {
    int p = blockIdx.y;
    const float* W = (p == 0) ? wqm : (p == 1) ? wkm : (p == 2) ? wqs : wks;
    int i = blockIdx.x * blockDim.x + threadIdx.x;
    float w = W[i];
    __nv_bfloat16 h = __float2bfloat16_rn(w);
    g_wh[p][i] = h;
    g_wl[p][i] = __float2bfloat16_rn(w - __bfloat162float(h));
}

// ---------------------------------------------------------------------------
// Kernel 1: projections Y = X @ W + b.  W hi/lo via cp.async (pre-split);
// X f32 -> bf16 hi/lo split in-kernel. 3-pass bf16 MMA, fp16 output.
// CTA: 64-row X tile, 2x4 warp grid (32x32 each), 2 CTAs/SM.
// ---------------------------------------------------------------------------
__global__ __launch_bounds__(PT, 2)
void proj_kernel(const float* __restrict__ query, const float* __restrict__ key,
                 const float* __restrict__ bqm, const float* __restrict__ bkm,
                 const float* __restrict__ bqs, const float* __restrict__ bks) {
    extern __shared__ __align__(16) char smem[];
    const int tid = threadIdx.x, wid = tid >> 5;
    const int p = blockIdx.y;
    const int m0 = blockIdx.x * 64;
    const uint32_t sbase = smem_u32(smem);

    const float* src  = (p & 1) ? key : query;
    const float* bias = (p == 0) ? bqm : (p == 1) ? bkm : (p == 2) ? bqs : bks;

    // W tiles via cp.async FIRST (overlap with X load/split below)
    load_tile_cp<128, PT>(sbase + P_WH, g_wh[p], tid);
    load_tile_cp<128, PT>(sbase + P_WL, g_wl[p], tid);
    cp_commit();

    float* sbias = reinterpret_cast<float*>(smem + P_BIAS);
    if (tid < 128) sbias[tid] = bias[tid];

    // X (64x128): f32 -> bf16 hi/lo split
#pragma unroll
    for (int i = 0; i < 4; i++) {
        int idx = i * PT + tid;
        int r = idx >> 4, c = idx & 15;
        const float* sp = src + (size_t)(m0 + r) * D_ + c * 8;
        float4 v0 = *reinterpret_cast<const float4*>(sp);
        float4 v1 = *reinterpret_cast<const float4*>(sp + 4);
        uint4 H, Lo;
        split2(v0.x, v0.y, H.x, Lo.x);
        split2(v0.z, v0.w, H.y, Lo.y);
        split2(v1.x, v1.y, H.z, Lo.z);
        split2(v1.z, v1.w, H.w, Lo.w);
        *reinterpret_cast<uint4*>(smem + P_XH + r * 272 + c * 16) = H;
        *reinterpret_cast<uint4*>(smem + P_XL + r * 272 + c * 16) = Lo;
    }
    cp_wait_group<0>();
    __syncthreads();

    const int wm = wid & 1, wn = wid >> 1;   // 2 x 4 warp grid -> 32 x 32 each
    const __nv_bfloat16* sXh = reinterpret_cast<const __nv_bfloat16*>(smem + P_XH);
    const __nv_bfloat16* sXl = reinterpret_cast<const __nv_bfloat16*>(smem + P_XL);
    const __nv_bfloat16* sWh = reinterpret_cast<const __nv_bfloat16*>(smem + P_WH);
    const __nv_bfloat16* sWl = reinterpret_cast<const __nv_bfloat16*>(smem + P_WL);

    FragC acc[2][2];
#pragma unroll
    for (int i = 0; i < 2; i++)
#pragma unroll
        for (int j = 0; j < 2; j++) wmma::fill_fragment(acc[i][j], 0.0f);

#pragma unroll
    for (int k = 0; k < 8; k++) {
        FragAb ah[2], al[2];
        wmma::load_matrix_sync(ah[0], sXh + (wm * 32 + 0) * LDB + k * 16, LDB);
        wmma::load_matrix_sync(ah[1], sXh + (wm * 32 + 16) * LDB + k * 16, LDB);
        wmma::load_matrix_sync(al[0], sXl + (wm * 32 + 0) * LDB + k * 16, LDB);
        wmma::load_matrix_sync(al[1], sXl + (wm * 32 + 16) * LDB + k * 16, LDB);
#pragma unroll
        for (int j = 0; j < 2; j++) {
            FragBrb bh, bl;
            wmma::load_matrix_sync(bh, sWh + (k * 16) * LDB + (wn * 32 + j * 16), LDB);
            wmma::load_matrix_sync(bl, sWl + (k * 16) * LDB + (wn * 32 + j * 16), LDB);
            wmma::mma_sync(acc[0][j], ah[0], bh, acc[0][j]);
            wmma::mma_sync(acc[1][j], ah[1], bh, acc[1][j]);
            wmma::mma_sync(acc[0][j], al[0], bh, acc[0][j]);
            wmma::mma_sync(acc[1][j], al[1], bh, acc[1][j]);
            wmma::mma_sync(acc[0][j], ah[0], bl, acc[0][j]);
            wmma::mma_sync(acc[1][j], ah[1], bl, acc[1][j]);
        }
    }
    __syncthreads();

    // C -> smem overlay (X area no longer needed)
    float* Cs = reinterpret_cast<float*>(smem + P_C);
#pragma unroll
    for (int i = 0; i < 2; i++)
#pragma unroll
        for (int j = 0; j < 2; j++)
            wmma::store_matrix_sync(Cs + (wm * 32 + i * 16) * LDC + (wn * 32 + j * 16),
                                    acc[i][j], LDC, wmma::mem_row_major);
    __syncthreads();

    // epilogue: + bias, fp16 round, store scratch (64 rows)
#pragma unroll
    for (int i = 0; i < 8; i++) {
        int u = i * PT + tid;
        int r = u >> 5, c4 = (u & 31) << 2;
        float4 v = *reinterpret_cast<const float4*>(Cs + r * LDC + c4);
        v.x += sbias[c4 + 0];
        v.y += sbias[c4 + 1];
        v.z += sbias[c4 + 2];
        v.w += sbias[c4 + 3];
        uint32_t h01 = pack2h(__float2half_rn(v.x), __float2half_rn(v.y));
        uint32_t h23 = pack2h(__float2half_rn(v.z), __float2half_rn(v.w));
        size_t o = (size_t)(m0 + r) * D_ + c4;
        *reinterpret_cast<uint2*>(g_p[p] + o) = make_uint2(h01, h23);
    }
}

// ---------------------------------------------------------------------------
// Kernel 2: scores (R14-proven shape). CTA = 128x128 S tile for ONE phase.
// 2 CTAs/SM. Single-pass fp16 GEMM, fp32 accumulate: S = Q @ K^T.
// Q/K cp.async issued FIRST; mask processed (two 64-row chunks staged in S1)
// entirely under the tile-load latency. Then one wait+barrier, MMA, epilogue.
// ---------------------------------------------------------------------------
__global__ __launch_bounds__(NT, 2)
void scores_kernel(const int* __restrict__ mask, float* __restrict__ out) {
    extern __shared__ __align__(16) char smem[];
    const int tid = threadIdx.x, wid = tid >> 5;
    const int nb0 = blockIdx.x * 128;
    const int mb0 = blockIdx.y * 128;
    const int b = blockIdx.z >> 1;
    const int phase = blockIdx.z & 1;
    const uint32_t sbase = smem_u32(smem);
    const int wm = wid & 3, wn = wid >> 2;   // 4 x 2 -> 32 x 64 per warp
    const float inv_sqrt_d = 0.08838834764831845f;

    const size_t qoff = ((size_t)b * L_ + mb0) * D_;
    const size_t koff = ((size_t)b * L_ + nb0) * D_;
    const int pq = 2 * phase, pk = 2 * phase + 1;

    // Issue tile loads FIRST — everything below overlaps their latency.
    load_tile_cp<128, NT>(sbase + S0, g_p[pq] + qoff, tid);
    load_tile_cp<128, NT>(sbase + S2, g_p[pk] + koff, tid);
    cp_commit();

    // Mask -> per-lane bitmask, staged through S1 in two 64-row chunks.
    float* Ms = reinterpret_cast<float*>(smem + S1);
    uint32_t mbits[2] = {0u, 0u};
#pragma unroll
    for (int half = 0; half < 2; half++) {
#pragma unroll
        for (int i = 0; i < 8; i++) {
            int u = i * NT + tid;
            int r = u >> 5, c4 = (u & 31) << 2;
            int4 mm = *reinterpret_cast<const int4*>(
                mask + ((size_t)b * L_ + mb0 + half * 64 + r) * L_ + nb0 + c4);
            float4 f;
            f.x = mm.x ? 1.0f : 0.0f;
            f.y = mm.y ? 1.0f : 0.0f;
            f.z = mm.z ? 1.0f : 0.0f;
            f.w = mm.w ? 1.0f : 0.0f;
            *reinterpret_cast<float4*>(Ms + r * LDC + c4) = f;
        }
        __syncthreads();
        if ((wm >> 1) == half) {
            int rbase = (wm & 1) * 32;
#pragma unroll
            for (int i = 0; i < 2; i++)
#pragma unroll
                for (int j = 0; j < 4; j++) {
                    FragC mf;
                    wmma::load_matrix_sync(
                        mf, Ms + (rbase + i * 16) * LDC + (wn * 64 + j * 16),
                        LDC, wmma::mem_row_major);
#pragma unroll
                    for (int e = 0; e < 8; e++)
                        mbits[i] |= (mf.x[e] != 0.0f ? 1u : 0u) << (j * 8 + e);
                }
        }
        __syncthreads();
    }

    cp_wait_group<0>();
    __syncthreads();   // tiles ready

    const __half* Qh = reinterpret_cast<const __half*>(smem + S0);
    const __half* Kh = reinterpret_cast<const __half*>(smem + S2);

    FragC acc[2][4];
#pragma unroll
    for (int i = 0; i < 2; i++)
#pragma unroll
        for (int j = 0; j < 4; j++) wmma::fill_fragment(acc[i][j], 0.0f);

#pragma unroll
    for (int k = 0; k < 8; k++) {
        FragAh a[2];
        wmma::load_matrix_sync(a[0], Qh + (wm * 32 + 0) * LDB + k * 16, LDB);
        wmma::load_matrix_sync(a[1], Qh + (wm * 32 + 16) * LDB + k * 16, LDB);
#pragma unroll
        for (int j = 0; j < 4; j++) {
            FragBch bf;   // K row-major [n][k] == col-major (k,n)
            wmma::load_matrix_sync(bf, Kh + (wn * 64 + j * 16) * LDB + k * 16, LDB);
            wmma::mma_sync(acc[0][j], a[0], bf, acc[0][j]);
            wmma::mma_sync(acc[1][j], a[1], bf, acc[1][j]);
        }
    }

    // epilogue: FMUL -> MUFU.TANH -> FFMA -> select -> store
    const float sA = phase ? 4.0f : 0.5f;
    const float sB = phase ? -6.0f : 0.5f;
    const float sC = phase ? -10.0f : 0.0f;
    float* obase = out + (size_t)phase * B_ * L_ * L_ + (size_t)b * L_ * L_;
#pragma unroll
    for (int i = 0; i < 2; i++) {
#pragma unroll
        for (int j = 0; j < 4; j++) {
            int r0 = wm * 32 + i * 16, c0 = wn * 64 + j * 16;
#pragma unroll
            for (int e = 0; e < 8; e++) {
                float t = tanh_hw(acc[i][j].x[e] * inv_sqrt_d);
                bool m = (mbits[i] >> (j * 8 + e)) & 1u;
                acc[i][j].x[e] = m ? fmaf(sA, t, sB) : sC;
            }
            wmma::store_matrix_sync(obase + (size_t)(mb0 + r0) * L_ + (nb0 + c0),
                                    acc[i][j], L_, wmma::mem_row_major);
        }
    }
}

// ---------------------------------------------------------------------------
extern "C" void kernel_launch(void* const* d_in, const int* in_sizes, int n_in,
                              void* d_out, int out_size) {
    const float* query = (const float*)d_in[0];
    const float* key   = (const float*)d_in[1];
    const int*   mask  = (const int*)d_in[2];
    const float* wqm = (const float*)d_in[3];
    const float* bqm = (const float*)d_in[4];
    const float* wkm = (const float*)d_in[5];
    const float* bkm = (const float*)d_in[6];
    const float* wqs = (const float*)d_in[7];
    const float* bqs = (const float*)d_in[8];
    const float* wks = (const float*)d_in[9];
    const float* bks = (const float*)d_in[10];
    float* out = (float*)d_out;

    cudaFuncSetAttribute(proj_kernel, cudaFuncAttributeMaxDynamicSharedMemorySize, P_SMEM);
    cudaFuncSetAttribute(scores_kernel, cudaFuncAttributeMaxDynamicSharedMemorySize, S_SMEM);

    wprep_kernel<<<dim3(64, 4), 256>>>(wqm, wkm, wqs, wks);
    proj_kernel<<<dim3((B_ * L_) / 64, 4), PT, P_SMEM>>>(
        query, key, bqm, bkm, bqs, bks);
    scores_kernel<<<dim3(L_ / 128, L_ / 128, 2 * B_), NT, S_SMEM>>>(mask, out);
}